// round 12
// baseline (speedup 1.0000x reference)
#include <cuda_runtime.h>

#define MAXN 50000
#define MAXE 1600000
#define RR 8

// Scratch: static device globals, referenced ONLY from device code.
__device__ __align__(16) float g_xw[(size_t)RR * MAXN * 64]; // [R][N][64] transformed feats
__device__ __align__(16) float g_h [(size_t)MAXN * 64];      // layer-1 output (pre-relu)
__device__ int g_cnt[MAXN * RR];       // (dst, relation) edge counts
__device__ int g_deg[MAXN];            // total in-degree per dst
__device__ int g_rowstart[MAXN];       // CSR row starts (block-local; add g_blocksum)
__device__ int g_fill[MAXN];           // fill cursors
__device__ int g_blocksum[512];        // scan partials (exclusive block offsets)
__device__ int g_eidx[MAXE];           // packed (src<<3)|rel, grouped by dst
__device__ int g_w64;                  // bit0: edge_type is int64, bit1: edge_index is int64

__device__ __forceinline__ int clampi(int v, int lo, int hi) {
    return min(max(v, lo), hi);
}

__device__ __forceinline__ void load_edge(const void* ei, const void* et, int E,
                                          int N, int e, int& src, int& dst, int& r) {
    int w = g_w64;
    if (w & 2) {
        const long long* p = (const long long*)ei;
        src = (int)p[e];
        dst = (int)p[(size_t)E + e];
    } else {
        const int* p = (const int*)ei;
        src = p[e];
        dst = p[(size_t)E + e];
    }
    if (w & 1) r = (int)((const long long*)et)[e];
    else       r = ((const int*)et)[e];
    src = clampi(src, 0, N - 1);
    dst = clampi(dst, 0, N - 1);
    r &= 7;
}

__device__ __forceinline__ unsigned long long bcast2(float x) {
    unsigned long long r;
    asm("mov.b64 %0, {%1, %1};" : "=l"(r) : "r"(__float_as_uint(x)));
    return r;
}
__device__ __forceinline__ void fma2(unsigned long long& d, unsigned long long a,
                                     unsigned long long b) {
    asm("fma.rn.f32x2 %0, %1, %2, %0;" : "+l"(d) : "l"(a), "l"(b));
}
__device__ __forceinline__ float lo2(unsigned long long v) {
    return __uint_as_float((unsigned)(v & 0xffffffffull));
}
__device__ __forceinline__ float hi2(unsigned long long v) {
    return __uint_as_float((unsigned)(v >> 32));
}

// ------------------------------------------------- dtype probe + zero (merged)
__global__ void dz_kernel(const void* ei, const void* et, int E, int N,
                          int n_cnt, int n_fill) {
    int i = blockIdx.x * blockDim.x + threadIdx.x;
    if (i < n_cnt) g_cnt[i] = 0;
    if (i < n_fill) g_fill[i] = 0;
    if (blockIdx.x == 0) {
        __shared__ int bad_et, bad_ei;
        if (threadIdx.x == 0) { bad_et = 0; bad_ei = 0; }
        __syncthreads();
        int M = min(E, 1024);
        const long long* et64 = (const long long*)et;
        const long long* ei64 = (const long long*)ei;
        for (int j = threadIdx.x; j < M; j += blockDim.x) {
            long long v = et64[j];
            if (v < 0 || v >= RR) bad_et = 1;
            long long s = ei64[j];
            if (s < 0 || s >= N) bad_ei = 1;
        }
        __syncthreads();
        if (threadIdx.x == 0) g_w64 = (bad_et ? 0 : 1) | (bad_ei ? 0 : 2);
    }
}

// ---------------------------------------------------------------- CSR build
__global__ void count_kernel(const void* ei, const void* et, int E, int N) {
    int e = blockIdx.x * blockDim.x + threadIdx.x;
    if (e < E) {
        int src, dst, r;
        load_edge(ei, et, E, N, e, src, dst, r);
        atomicAdd(&g_cnt[dst * RR + r], 1);
    }
}

__global__ void scan1_kernel(int N) {
    __shared__ int s[512];
    int d = blockIdx.x * 512 + threadIdx.x;
    int deg = 0;
    if (d < N) {
        for (int r = 0; r < RR; r++) deg += g_cnt[d * RR + r];
    }
    s[threadIdx.x] = deg;
    __syncthreads();
    for (int off = 1; off < 512; off <<= 1) {
        int v = (threadIdx.x >= off) ? s[threadIdx.x - off] : 0;
        __syncthreads();
        s[threadIdx.x] += v;
        __syncthreads();
    }
    int incl = s[threadIdx.x];
    if (d < N) { g_rowstart[d] = incl - deg; g_deg[d] = deg; }
    if (threadIdx.x == 511) g_blocksum[blockIdx.x] = incl;
}

__global__ void scan2_kernel(int nb) {
    __shared__ int s[512];
    int v = (threadIdx.x < nb) ? g_blocksum[threadIdx.x] : 0;
    s[threadIdx.x] = v;
    __syncthreads();
    for (int off = 1; off < 512; off <<= 1) {
        int p = (threadIdx.x >= off) ? s[threadIdx.x - off] : 0;
        __syncthreads();
        s[threadIdx.x] += p;
        __syncthreads();
    }
    if (threadIdx.x < nb) g_blocksum[threadIdx.x] = s[threadIdx.x] - v; // exclusive
}

__global__ void fill_kernel(const void* ei, const void* et, int E, int N) {
    int e = blockIdx.x * blockDim.x + threadIdx.x;
    if (e < E) {
        int src, dst, r;
        load_edge(ei, et, E, N, e, src, dst, r);
        int base = g_rowstart[dst] + g_blocksum[dst >> 9];
        int pos  = base + atomicAdd(&g_fill[dst], 1);
        pos = clampi(pos, 0, E - 1);
        g_eidx[pos] = (src << 3) | r;
    }
}

// ---------------------------------------------------------------- GEMM (f32x2)
// g_xw[r] = X @ Wrel[r] (r=0..7), plus root: X @ Wroot + b into rootout.
// LAYER1: X = Xarg, rootout = g_h. LAYER2: X = relu(g_h), rootout = Oarg.
// X tile TRANSPOSED in dynamic smem: xs[k][node], 136-float padded rows.
// 128 threads -> 128 nodes x 64 cols; thread: 16 nodes x 4 cols.
// Per k: 1 LDG.128 (W) + 4 LDS.128 (x) + 4 bcast + 32 independent FFMA2
// => twice the latency-hiding window per W load vs the 8-node tile.
template <int K, int LAYER>
__global__ void __launch_bounds__(128)
gemm_kernel(const float* __restrict__ Xarg,
            const float* __restrict__ Wrel,
            const float* __restrict__ Wroot,
            const float* __restrict__ bias,
            float* __restrict__ Oarg, int N) {
    const float* X = (LAYER == 1) ? Xarg : g_h;
    float* rootout = (LAYER == 1) ? g_h : Oarg;

    extern __shared__ float xs[];   // [K][136]
    const int PITCH = 136;
    int n0 = blockIdx.x * 128;

    // Load + transpose X tile: thread t handles row t for every 4-col chunk q.
    // STS addresses = (4q+j)*PITCH + t  -> lane-consecutive, bank-conflict-free.
    for (int q = 0; q < K / 4; q++) {
        int row = threadIdx.x;
        float4 v = make_float4(0.f, 0.f, 0.f, 0.f);
        if (n0 + row < N)
            v = reinterpret_cast<const float4*>(X)[(size_t)(n0 + row) * (K / 4) + q];
        if (LAYER == 2) {
            v.x = fmaxf(v.x, 0.f); v.y = fmaxf(v.y, 0.f);
            v.z = fmaxf(v.z, 0.f); v.w = fmaxf(v.w, 0.f);
        }
        xs[(4 * q + 0) * PITCH + row] = v.x;
        xs[(4 * q + 1) * PITCH + row] = v.y;
        xs[(4 * q + 2) * PITCH + row] = v.z;
        xs[(4 * q + 3) * PITCH + row] = v.w;
    }
    __syncthreads();

    int cg = threadIdx.x & 15;  // column group: cols [cg*4, cg*4+4)
    int i  = threadIdx.x >> 4;  // node group: nodes [i*16, i*16+16)

    for (int r = 0; r < 9; r++) {
        const float* W = (r < 8) ? (Wrel + (size_t)r * K * 64) : Wroot;
        unsigned long long acc[4][8];   // [col j][node-pair p]
#pragma unroll
        for (int j = 0; j < 4; j++)
#pragma unroll
            for (int p = 0; p < 8; p++) acc[j][p] = 0ull;

#pragma unroll 4
        for (int k = 0; k < K; k++) {
            float4 wv = *reinterpret_cast<const float4*>(W + (size_t)k * 64 + cg * 4);
            unsigned long long wb[4] = {bcast2(wv.x), bcast2(wv.y),
                                        bcast2(wv.z), bcast2(wv.w)};
            const ulonglong2* xp =
                reinterpret_cast<const ulonglong2*>(&xs[k * PITCH + i * 16]);
            ulonglong2 xa = xp[0], xb = xp[1], xc = xp[2], xd = xp[3];
            unsigned long long xpair[8] = {xa.x, xa.y, xb.x, xb.y,
                                           xc.x, xc.y, xd.x, xd.y};
#pragma unroll
            for (int j = 0; j < 4; j++)
#pragma unroll
                for (int p = 0; p < 8; p++)
                    fma2(acc[j][p], xpair[p], wb[j]);
        }

#pragma unroll
        for (int n = 0; n < 16; n++) {
            int node = n0 + i * 16 + n;
            if (node < N) {
                int p = n >> 1;
                float c0 = (n & 1) ? hi2(acc[0][p]) : lo2(acc[0][p]);
                float c1 = (n & 1) ? hi2(acc[1][p]) : lo2(acc[1][p]);
                float c2 = (n & 1) ? hi2(acc[2][p]) : lo2(acc[2][p]);
                float c3 = (n & 1) ? hi2(acc[3][p]) : lo2(acc[3][p]);
                if (r < 8) {
                    *reinterpret_cast<float4*>(
                        g_xw + ((size_t)r * N + node) * 64 + cg * 4) =
                        make_float4(c0, c1, c2, c3);
                } else {
                    float4 b = reinterpret_cast<const float4*>(bias)[cg];
                    *reinterpret_cast<float4*>(
                        rootout + (size_t)node * 64 + cg * 4) =
                        make_float4(c0 + b.x, c1 + b.y, c2 + b.z, c3 + b.w);
                }
            }
        }
    }
}

// ---------------------------------------------------------------- Aggregation
// One WARP per dst node (no intra-warp divergence); lane handles 2 cols (float2).
// Unrolled x4: four independent 256B gathers in flight; two accumulator chains.
template <int LAYER>
__global__ void agg_kernel(float* __restrict__ Oarg, int N) {
    float* inout = (LAYER == 1) ? g_h : Oarg;

    int dst  = blockIdx.x * 8 + (threadIdx.x >> 5);
    int lane = threadIdx.x & 31;
    if (dst >= N) return;

    int start = g_rowstart[dst] + g_blocksum[dst >> 9];
    int dg    = g_deg[dst];

    float inv[RR];
#pragma unroll
    for (int r = 0; r < RR; r++) {
        int c = g_cnt[dst * RR + r];
        inv[r] = 1.0f / (float)(c > 0 ? c : 1);
    }

    const float* base = g_xw + (size_t)lane * 2;
    float2 accA = make_float2(0.f, 0.f);
    float2 accB = make_float2(0.f, 0.f);

    int i = 0;
    for (; i + 4 <= dg; i += 4) {
        int e0 = g_eidx[start + i];
        int e1 = g_eidx[start + i + 1];
        int e2 = g_eidx[start + i + 2];
        int e3 = g_eidx[start + i + 3];
        float2 v0 = *reinterpret_cast<const float2*>(
            base + ((size_t)(e0 & 7) * N + (e0 >> 3)) * 64);
        float2 v1 = *reinterpret_cast<const float2*>(
            base + ((size_t)(e1 & 7) * N + (e1 >> 3)) * 64);
        float2 v2 = *reinterpret_cast<const float2*>(
            base + ((size_t)(e2 & 7) * N + (e2 >> 3)) * 64);
        float2 v3 = *reinterpret_cast<const float2*>(
            base + ((size_t)(e3 & 7) * N + (e3 >> 3)) * 64);
        float s0 = inv[e0 & 7], s1 = inv[e1 & 7], s2 = inv[e2 & 7], s3 = inv[e3 & 7];
        accA.x = fmaf(v0.x, s0, accA.x); accA.y = fmaf(v0.y, s0, accA.y);
        accB.x = fmaf(v1.x, s1, accB.x); accB.y = fmaf(v1.y, s1, accB.y);
        accA.x = fmaf(v2.x, s2, accA.x); accA.y = fmaf(v2.y, s2, accA.y);
        accB.x = fmaf(v3.x, s3, accB.x); accB.y = fmaf(v3.y, s3, accB.y);
    }
    for (; i < dg; i++) {
        int e0 = g_eidx[start + i];
        float s0 = inv[e0 & 7];
        float2 v0 = *reinterpret_cast<const float2*>(
            base + ((size_t)(e0 & 7) * N + (e0 >> 3)) * 64);
        accA.x = fmaf(v0.x, s0, accA.x); accA.y = fmaf(v0.y, s0, accA.y);
    }

    float2* o = reinterpret_cast<float2*>(inout + (size_t)dst * 64 + lane * 2);
    float2 old = *o;
    old.x += accA.x + accB.x;
    old.y += accA.y + accB.y;
    *o = old;
}

// ---------------------------------------------------------------- launch
extern "C" void kernel_launch(void* const* d_in, const int* in_sizes, int n_in,
                              void* d_out, int out_size) {
    const float* x   = (const float*)d_in[0];
    const void*  ei  = d_in[1];
    const void*  et  = d_in[2];
    const float* W1r = (const float*)d_in[3];
    const float* W1o = (const float*)d_in[4];
    const float* b1  = (const float*)d_in[5];
    const float* W2r = (const float*)d_in[6];
    const float* W2o = (const float*)d_in[7];
    const float* b2  = (const float*)d_in[8];
    float* out = (float*)d_out;

    int N = in_sizes[0] / 128;
    int E = in_sizes[2];

    int nb = (N + 511) / 512;
    int gb = (N + 127) / 128;
    int ab = (N + 7) / 8;

    const int SM1 = 128 * 136 * 4;   // 69.6 KB (K=128)
    const int SM2 = 64 * 136 * 4;    // 34.8 KB (K=64)
    static bool attr_set = false;
    if (!attr_set) {
        cudaFuncSetAttribute(gemm_kernel<128, 1>,
                             cudaFuncAttributeMaxDynamicSharedMemorySize, SM1);
        cudaFuncSetAttribute(gemm_kernel<64, 2>,
                             cudaFuncAttributeMaxDynamicSharedMemorySize, SM2);
        attr_set = true;
    }

    // gemm1 kept at launch index 3 (ncu capture window). Deps preserved on stream 0.
    dz_kernel<<<(N * RR + 255) / 256, 256>>>(ei, et, E, N, N * RR, N);      // 0
    count_kernel<<<(E + 255) / 256, 256>>>(ei, et, E, N);                    // 1
    scan1_kernel<<<nb, 512>>>(N);                                            // 2
    gemm_kernel<128, 1><<<gb, 128, SM1>>>(x, W1r, W1o, b1, nullptr, N);      // 3
    scan2_kernel<<<1, 512>>>(nb);                                            // 4
    fill_kernel<<<(E + 255) / 256, 256>>>(ei, et, E, N);                     // 5
    agg_kernel<1><<<ab, 256>>>(nullptr, N);                                  // 6
    gemm_kernel<64, 2><<<gb, 128, SM2>>>(nullptr, W2r, W2o, b2, out, N);     // 7
    agg_kernel<2><<<ab, 256>>>(out, N);                                      // 8
}